// round 13
// baseline (speedup 1.0000x reference)
#include <cuda_runtime.h>
#include <cuda_bf16.h>
#include <stdint.h>
#include <math.h>

// TriangularSylvesterNeRF  Z=32 K=4 H=128 B=32768
// mma.sync bf16 split-precision; flow fused into GEMM fragments (no D smem
// roundtrip); 3-buffer cp.async pipeline; 2 CTAs/SM.

#define ZZ 32
#define KK 4
#define HH 128
#define TM 64
#define NTH 256
#define NCTA 512

// ---- smem byte offsets ----
#define OFF_B   0          /* 3 x 32KB B buffers */
#define OFF_BB  98304      /* 3 x 256B bias slots */
#define OFF_Z   99072      /* [64][34] f32 = 8704 */
#define OFF_LD  107776     /* [64] f32 = 256 */
#define SMEM_TOTAL 108032

// ---- fragment-linear weight images, interleaved {hi.x,hi.y,lo.x,lo.y} ----
// main: [k][hc 0..15][slot=ks*8+ntl][lane]; col n = hc*64 + ntl*8 + (lane>>2),
// global ordering n = j*32 + i.
__device__ uint4 g_Wm[KK][16][64][32];
__device__ uint4 g_Wg[3][2][64][32];
__device__ __align__(16) float g_bdre[KK][16][64];
__device__ float g_bdiag[3][128];
// per-CTA diag scratch: [blk][{d1,d2,b}][kj 0..127][sample 0..63]
__device__ float g_dg[NCTA][3][128][64];

__device__ __forceinline__ uint32_t pack2(float a, float b) {
    return (uint32_t)__bfloat16_as_ushort(__float2bfloat16(a)) |
           ((uint32_t)__bfloat16_as_ushort(__float2bfloat16(b)) << 16);
}
__device__ __forceinline__ float bres(float x) {
    return x - __bfloat162float(__float2bfloat16(x));
}

__global__ void prep_kernel(const float* __restrict__ Wd, const float* __restrict__ bd,
                            const float* __restrict__ Wd1, const float* __restrict__ bd1,
                            const float* __restrict__ Wd2, const float* __restrict__ bd2,
                            const float* __restrict__ Wb, const float* __restrict__ bb)
{
    int idx = blockIdx.x * blockDim.x + threadIdx.x;
    if (idx < 131072) {
        int lane = idx & 31, slot = (idx >> 5) & 63, hc = (idx >> 11) & 15, k = idx >> 15;
        int ks = slot >> 3, ntl = slot & 7, g = lane >> 2, t = lane & 3;
        int n = hc * 64 + ntl * 8 + g;
        int j = n >> 5, i = n & 31;
        const float* src = Wd + (size_t)((i * ZZ + j) * KK + k) * HH + ks * 16 + 2 * t;
        float f0 = src[0], f1 = src[1], f2 = src[8], f3 = src[9];
        g_Wm[k][hc][slot][lane] = make_uint4(pack2(f0, f1), pack2(f2, f3),
                                             pack2(bres(f0), bres(f1)),
                                             pack2(bres(f2), bres(f3)));
    } else if (idx < 131072 + 12288) {
        int r = idx - 131072;
        int lane = r & 31, slot = (r >> 5) & 63, half = (r >> 11) & 1, m = r >> 12;
        int ks = slot >> 3, ntl = slot & 7, g = lane >> 2, t = lane & 3;
        int n = half * 64 + ntl * 8 + g;     // n = kq*32 + j
        int kq = n >> 5, j = n & 31;
        const float* W = (m == 0) ? Wd1 : (m == 1) ? Wd2 : Wb;
        const float* src = W + (size_t)(j * KK + kq) * HH + ks * 16 + 2 * t;
        float f0 = src[0], f1 = src[1], f2 = src[8], f3 = src[9];
        g_Wg[m][half][slot][lane] = make_uint4(pack2(f0, f1), pack2(f2, f3),
                                               pack2(bres(f0), bres(f1)),
                                               pack2(bres(f2), bres(f3)));
    } else if (idx < 131072 + 12288 + 4096) {
        int r = idx - 131072 - 12288;
        int l = r & 63, hc = (r >> 6) & 15, k = r >> 10;
        int n = hc * 64 + l;
        int j = n >> 5, i = n & 31;
        g_bdre[k][hc][l] = bd[(i * ZZ + j) * KK + k];
    } else if (idx < 131072 + 12288 + 4096 + 384) {
        int r = idx - 147456;
        int n = r & 127, m = r >> 7;
        int kq = n >> 5, j = n & 31;
        const float* bv = (m == 0) ? bd1 : (m == 1) ? bd2 : bb;
        g_bdiag[m][n] = bv[j * KK + kq];
    }
}

__device__ __forceinline__ void mma_bf16(float c[4], const uint32_t a[4],
                                         uint32_t b0, uint32_t b1) {
    asm volatile(
        "mma.sync.aligned.m16n8k16.row.col.f32.bf16.bf16.f32 "
        "{%0,%1,%2,%3}, {%4,%5,%6,%7}, {%8,%9}, {%0,%1,%2,%3};"
        : "+f"(c[0]), "+f"(c[1]), "+f"(c[2]), "+f"(c[3])
        : "r"(a[0]), "r"(a[1]), "r"(a[2]), "r"(a[3]), "r"(b0), "r"(b1));
}
__device__ __forceinline__ void cp16(uint32_t dst, const void* src) {
    asm volatile("cp.async.cg.shared.global [%0], [%1], 16;" :: "r"(dst), "l"(src));
}
#define CP_COMMIT() asm volatile("cp.async.commit_group;" ::: "memory")
#define CP_WAIT0()  asm volatile("cp.async.wait_group 0;" ::: "memory")
#define CP_WAIT1()  asm volatile("cp.async.wait_group 1;" ::: "memory")

__device__ __forceinline__ uint32_t smem_u32(const void* p) {
    uint32_t a;
    asm("{ .reg .u64 t; cvta.to.shared.u64 t, %1; cvt.u32.u64 %0, t; }" : "=r"(a) : "l"(p));
    return a;
}

// Half-chunk GEMM: warp tile 16 rows x 32 cols, quad-interleaved MMA order.
__device__ __forceinline__ void gemm_h(const uint4* __restrict__ Bq,
                                       int lane, int nq,
                                       const uint32_t aH[8][4],
                                       const uint32_t aL[8][4],
                                       float acc[4][4])
{
    #pragma unroll
    for (int q = 0; q < 4; q++)
        acc[q][0] = acc[q][1] = acc[q][2] = acc[q][3] = 0.f;
    #pragma unroll
    for (int ks = 0; ks < 8; ks++) {
        const int base = ks * 8 + nq * 4;
        uint4 b0 = Bq[(base + 0) * 32 + lane];
        uint4 b1 = Bq[(base + 1) * 32 + lane];
        uint4 b2 = Bq[(base + 2) * 32 + lane];
        uint4 b3 = Bq[(base + 3) * 32 + lane];
        mma_bf16(acc[0], aH[ks], b0.x, b0.y);
        mma_bf16(acc[1], aH[ks], b1.x, b1.y);
        mma_bf16(acc[2], aH[ks], b2.x, b2.y);
        mma_bf16(acc[3], aH[ks], b3.x, b3.y);
        mma_bf16(acc[0], aH[ks], b0.z, b0.w);
        mma_bf16(acc[1], aH[ks], b1.z, b1.w);
        mma_bf16(acc[2], aH[ks], b2.z, b2.w);
        mma_bf16(acc[3], aH[ks], b3.z, b3.w);
        mma_bf16(acc[0], aL[ks], b0.x, b0.y);
        mma_bf16(acc[1], aL[ks], b1.x, b1.y);
        mma_bf16(acc[2], aL[ks], b2.x, b2.y);
        mma_bf16(acc[3], aL[ks], b3.x, b3.y);
    }
}

__device__ __forceinline__ void stage32k(uint32_t dst, const void* srcv, int tid) {
    const char* s = (const char*)srcv;
    #pragma unroll
    for (int r = 0; r < 8; r++) {
        int i = r * NTH + tid;
        cp16(dst + i * 16, s + i * 16);
    }
}
__device__ __forceinline__ void stage_main(uint32_t sb, int buf, int hcg, int tid) {
    int k2 = hcg >> 4, hc = hcg & 15;
    stage32k(sb + OFF_B + buf * 32768, &g_Wm[k2][hc][0][0], tid);
    if (tid < 16)
        cp16(sb + OFF_BB + buf * 256 + tid * 16,
             (const char*)&g_bdre[k2][hc][0] + tid * 16);
}

__global__ __launch_bounds__(NTH, 2)
void sylv_main(const float* __restrict__ z0, const float* __restrict__ h,
               float* __restrict__ out_z, float* __restrict__ out_ld)
{
    extern __shared__ char sm[];
    const uint32_t sb = smem_u32(sm);
    float* zsm  = (float*)(sm + OFF_Z);
    float* ldsm = (float*)(sm + OFF_LD);

    const int tid = threadIdx.x, w = tid >> 5, lane = tid & 31;
    const int g = lane >> 2, t = lane & 3;
    const int r0 = (w & 3) * 16;           // GEMM row base
    const int nq = w >> 2;                 // j-half (0/1)
    const int blk = blockIdx.x;
    const int m0 = blk * TM;
    const int mA = r0 + g, mB = r0 + g + 8;  // this thread's 2 samples

    // ---- A fragments (persist): split bf16 hi/lo ----
    uint32_t aH[8][4], aL[8][4];
    {
        const float* hp = h + (size_t)m0 * HH;
        #pragma unroll
        for (int ks = 0; ks < 8; ks++) {
            int k0 = ks * 16 + 2 * t;
            const float* p0 = hp + (size_t)mA * HH + k0;
            const float* p1 = hp + (size_t)mB * HH + k0;
            float2 x0 = *(const float2*)p0;
            float2 x1 = *(const float2*)p1;
            float2 x2 = *(const float2*)(p0 + 8);
            float2 x3 = *(const float2*)(p1 + 8);
            aH[ks][0] = pack2(x0.x, x0.y); aL[ks][0] = pack2(bres(x0.x), bres(x0.y));
            aH[ks][1] = pack2(x1.x, x1.y); aL[ks][1] = pack2(bres(x1.x), bres(x1.y));
            aH[ks][2] = pack2(x2.x, x2.y); aL[ks][2] = pack2(bres(x2.x), bres(x2.y));
            aH[ks][3] = pack2(x3.x, x3.y); aL[ks][3] = pack2(bres(x3.x), bres(x3.y));
        }
    }
    // ---- z into smem (pitch 34) ----
    for (int idx = tid; idx < TM * ZZ; idx += NTH)
        zsm[(idx >> 5) * 34 + (idx & 31)] = z0[(size_t)(m0 + (idx >> 5)) * ZZ + (idx & 31)];

    // ---- diag GEMMs (6 half-chunks, buffers 0/1) -> global scratch ----
    stage32k(sb + OFF_B, &g_Wg[0][0][0][0], tid);
    CP_COMMIT();
    for (int d = 0; d < 6; d++) {
        if (d < 5) {
            int dn = d + 1;
            stage32k(sb + OFF_B + (dn & 1) * 32768, &g_Wg[dn >> 1][dn & 1][0][0], tid);
            CP_COMMIT(); CP_WAIT1();
        } else {
            CP_WAIT0();
        }
        __syncthreads();
        {
            int mm = d >> 1, half = d & 1;
            float acc[4][4];
            gemm_h((const uint4*)(sm + OFF_B + (d & 1) * 32768), lane, nq, aH, aL, acc);
            #pragma unroll
            for (int ntl = 0; ntl < 4; ntl++) {
                int lc = nq * 32 + ntl * 8 + 2 * t;
                int n = half * 64 + lc;
                float b0v = g_bdiag[mm][n], b1v = g_bdiag[mm][n + 1];
                float v0 = acc[ntl][0] + b0v, v1 = acc[ntl][1] + b1v;
                float v2 = acc[ntl][2] + b0v, v3 = acc[ntl][3] + b1v;
                if (mm < 2) { v0 = tanhf(v0); v1 = tanhf(v1); v2 = tanhf(v2); v3 = tanhf(v3); }
                g_dg[blk][mm][n][mA]     = v0;
                g_dg[blk][mm][n + 1][mA] = v1;
                g_dg[blk][mm][n][mB]     = v2;
                g_dg[blk][mm][n + 1][mB] = v3;
            }
        }
        __syncthreads();
    }

    // ---- prologue: stage half-chunks 0,1 ----
    stage_main(sb, 0, 0, tid); CP_COMMIT();
    stage_main(sb, 1, 1, tid); CP_COMMIT();
    CP_WAIT1();
    __syncthreads();

    // ---- main loop over 64 half-chunks; flow fused into fragments ----
    float dzA[8], dzB[8], ldA = 0.f, ldB = 0.f;
    #pragma unroll
    for (int il = 0; il < 8; il++) { dzA[il] = 0.f; dzB[il] = 0.f; }

    #pragma unroll 1
    for (int cc = 0; cc < 64; cc++) {
        const int k = cc >> 4, hc = cc & 15, flip = k & 1;
        const int j = hc * 2 + nq, kj = k * 32 + j;

        if (cc <= 61) stage_main(sb, (cc + 2) % 3, cc + 2, tid);

        // diag/bias loads for this (kj, samples) — issue early
        float d1A = g_dg[blk][0][kj][mA], d1B = g_dg[blk][0][kj][mB];
        float d2A = g_dg[blk][1][kj][mA], d2B = g_dg[blk][1][kj][mB];
        float bvA = g_dg[blk][2][kj][mA], bvB = g_dg[blk][2][kj][mB];

        float acc[4][4];
        gemm_h((const uint4*)(sm + OFF_B + (cc % 3) * 32768), lane, nq, aH, aL, acc);

        // bias -> Dv; pre partial over this thread's 8 i's
        const float2* bbp = (const float2*)(sm + OFF_BB + (cc % 3) * 256);
        float DvA[8], DvB[8];
        float preA = 0.f, preB = 0.f;
        #pragma unroll
        for (int ntl = 0; ntl < 4; ntl++) {
            float2 bb = bbp[nq * 16 + ntl * 4 + t];
            int i0 = ntl * 8 + 2 * t, i1 = i0 + 1;
            float dA0 = acc[ntl][0] + bb.x, dA1 = acc[ntl][1] + bb.y;
            float dB0 = acc[ntl][2] + bb.x, dB1 = acc[ntl][3] + bb.y;
            DvA[2*ntl] = dA0; DvA[2*ntl+1] = dA1;
            DvB[2*ntl] = dB0; DvB[2*ntl+1] = dB1;
            int zi = flip ? (30 - i0) : i0;
            float2 zqA = *(const float2*)&zsm[mA * 34 + zi];
            float2 zqB = *(const float2*)&zsm[mB * 34 + zi];
            float zA0 = flip ? zqA.y : zqA.x, zA1 = flip ? zqA.x : zqA.y;
            float zB0 = flip ? zqB.y : zqB.x, zB1 = flip ? zqB.x : zqB.y;
            preA = fmaf(zA0, (i0 > j) ? dA0 : 0.f, preA);
            preA = fmaf(zA1, (i1 > j) ? dA1 : 0.f, preA);
            preB = fmaf(zB0, (i0 > j) ? dB0 : 0.f, preB);
            preB = fmaf(zB1, (i1 > j) ? dB1 : 0.f, preB);
        }
        preA += __shfl_xor_sync(0xffffffffu, preA, 1);
        preA += __shfl_xor_sync(0xffffffffu, preA, 2);
        preB += __shfl_xor_sync(0xffffffffu, preB, 1);
        preB += __shfl_xor_sync(0xffffffffu, preB, 2);
        float zpjA = zsm[mA * 34 + (flip ? 31 - j : j)];
        float zpjB = zsm[mB * 34 + (flip ? 31 - j : j)];
        float tA = tanhf(preA + bvA + zpjA * d2A);
        float tB = tanhf(preB + bvB + zpjB * d2B);
        ldA += logf(fabsf(fmaf(1.f - tA * tA, d1A * d2A, 1.f)));
        ldB += logf(fabsf(fmaf(1.f - tB * tB, d1B * d2B, 1.f)));
        #pragma unroll
        for (int ntl = 0; ntl < 4; ntl++) {
            int i0 = ntl * 8 + 2 * t, i1 = i0 + 1;
            float cA0 = (i0 < j) ? DvA[2*ntl]   : ((i0 == j) ? d1A : 0.f);
            float cA1 = (i1 < j) ? DvA[2*ntl+1] : ((i1 == j) ? d1A : 0.f);
            float cB0 = (i0 < j) ? DvB[2*ntl]   : ((i0 == j) ? d1B : 0.f);
            float cB1 = (i1 < j) ? DvB[2*ntl+1] : ((i1 == j) ? d1B : 0.f);
            dzA[2*ntl]   = fmaf(tA, cA0, dzA[2*ntl]);
            dzA[2*ntl+1] = fmaf(tA, cA1, dzA[2*ntl+1]);
            dzB[2*ntl]   = fmaf(tB, cB0, dzB[2*ntl]);
            dzB[2*ntl+1] = fmaf(tB, cB1, dzB[2*ntl+1]);
        }

        // k-boundary: two-phase dz merge into z (nq groups serialize)
        if (hc == 15) {
            if (nq == 0) {
                #pragma unroll
                for (int ntl = 0; ntl < 4; ntl++) {
                    int i0 = ntl * 8 + 2 * t;
                    int x0 = flip ? 31 - i0 : i0, x1 = flip ? 30 - i0 : i0 + 1;
                    zsm[mA * 34 + x0] += dzA[2*ntl];
                    zsm[mA * 34 + x1] += dzA[2*ntl+1];
                    zsm[mB * 34 + x0] += dzB[2*ntl];
                    zsm[mB * 34 + x1] += dzB[2*ntl+1];
                }
            }
            __syncthreads();
            if (nq == 1) {
                #pragma unroll
                for (int ntl = 0; ntl < 4; ntl++) {
                    int i0 = ntl * 8 + 2 * t;
                    int x0 = flip ? 31 - i0 : i0, x1 = flip ? 30 - i0 : i0 + 1;
                    zsm[mA * 34 + x0] += dzA[2*ntl];
                    zsm[mA * 34 + x1] += dzA[2*ntl+1];
                    zsm[mB * 34 + x0] += dzB[2*ntl];
                    zsm[mB * 34 + x1] += dzB[2*ntl+1];
                }
            }
            #pragma unroll
            for (int il = 0; il < 8; il++) { dzA[il] = 0.f; dzB[il] = 0.f; }
        }

        CP_COMMIT(); CP_WAIT1();
        __syncthreads();
    }

    // ---- outputs ----
    if (nq == 0 && t == 0) { ldsm[mA] = ldA; ldsm[mB] = ldB; }
    __syncthreads();
    if (nq == 1 && t == 0) {
        out_ld[m0 + mA] = ldsm[mA] + ldA;
        out_ld[m0 + mB] = ldsm[mB] + ldB;
    }
    for (int idx = tid; idx < TM * ZZ; idx += NTH)
        out_z[(size_t)(m0 + (idx >> 5)) * ZZ + (idx & 31)] = zsm[(idx >> 5) * 34 + (idx & 31)];
}

extern "C" void kernel_launch(void* const* d_in, const int* in_sizes, int n_in,
                              void* d_out, int out_size)
{
    const float* z0  = (const float*)d_in[0];
    const float* h   = (const float*)d_in[1];
    const float* Wd  = (const float*)d_in[2];
    const float* bd  = (const float*)d_in[3];
    const float* Wd1 = (const float*)d_in[4];
    const float* bd1 = (const float*)d_in[5];
    const float* Wd2 = (const float*)d_in[6];
    const float* bd2 = (const float*)d_in[7];
    const float* Wb  = (const float*)d_in[8];
    const float* bb  = (const float*)d_in[9];

    const int B = in_sizes[0] / ZZ;          // 32768
    float* out_z  = (float*)d_out;
    float* out_ld = (float*)d_out + (size_t)B * ZZ;

    int prep_elems = 131072 + 12288 + 4096 + 384;
    prep_kernel<<<(prep_elems + 255) / 256, 256>>>(Wd, bd, Wd1, bd1, Wd2, bd2, Wb, bb);

    cudaFuncSetAttribute(sylv_main, cudaFuncAttributeMaxDynamicSharedMemorySize, SMEM_TOTAL);
    sylv_main<<<B / TM, NTH, SMEM_TOTAL>>>(z0, h, out_z, out_ld);
}

// round 17
// speedup vs baseline: 1.0186x; 1.0186x over previous
#include <cuda_runtime.h>
#include <cuda_bf16.h>
#include <stdint.h>
#include <math.h>

// TriangularSylvesterNeRF  Z=32 K=4 H=128 B=32768
// mma.sync bf16 split-precision; 64-col half-chunks; 2 CTAs/SM.
// Round 16 (= round 14 resubmit; two broker-side container failures):
// barrier moved before gemm (flow at iteration end), XOR flip, hoisted pointers.

#define ZZ 32
#define KK 4
#define HH 128
#define TM 64
#define NTH 256
#define NCTA 512
#define DP 68            /* D row pitch (floats) */

// ---- smem byte offsets ----
#define OFF_B0 0         /* 32KB interleaved hi/lo */
#define OFF_B1 32768
#define OFF_D0 65536     /* [64][68] f32 = 17408 */
#define OFF_D1 82944
#define OFF_Z  100352    /* [64][33] f32 = 8448 */
#define OFF_BB 108800    /* bias slots [2][64] f32 */
#define SMEM_TOTAL 109312

// ---- fragment-linear weight images, interleaved {hi.x,hi.y,lo.x,lo.y} ----
__device__ uint4 g_Wm[KK][16][64][32];
__device__ uint4 g_Wg[3][2][64][32];
__device__ __align__(16) float g_bdre[KK][16][64];
__device__ float g_bdiag[3][128];
__device__ float g_dg[NCTA][3][128][64];

__device__ __forceinline__ uint32_t pack2(float a, float b) {
    return (uint32_t)__bfloat16_as_ushort(__float2bfloat16(a)) |
           ((uint32_t)__bfloat16_as_ushort(__float2bfloat16(b)) << 16);
}
__device__ __forceinline__ float bres(float x) {
    return x - __bfloat162float(__float2bfloat16(x));
}

__global__ void prep_kernel(const float* __restrict__ Wd, const float* __restrict__ bd,
                            const float* __restrict__ Wd1, const float* __restrict__ bd1,
                            const float* __restrict__ Wd2, const float* __restrict__ bd2,
                            const float* __restrict__ Wb, const float* __restrict__ bb)
{
    int idx = blockIdx.x * blockDim.x + threadIdx.x;
    if (idx < 131072) {
        int lane = idx & 31, slot = (idx >> 5) & 63, hc = (idx >> 11) & 15, k = idx >> 15;
        int ks = slot >> 3, ntl = slot & 7, g = lane >> 2, t = lane & 3;
        int n = hc * 64 + ntl * 8 + g;
        int j = n >> 5, i = n & 31;
        const float* src = Wd + (size_t)((i * ZZ + j) * KK + k) * HH + ks * 16 + 2 * t;
        float f0 = src[0], f1 = src[1], f2 = src[8], f3 = src[9];
        g_Wm[k][hc][slot][lane] = make_uint4(pack2(f0, f1), pack2(f2, f3),
                                             pack2(bres(f0), bres(f1)),
                                             pack2(bres(f2), bres(f3)));
    } else if (idx < 131072 + 12288) {
        int r = idx - 131072;
        int lane = r & 31, slot = (r >> 5) & 63, half = (r >> 11) & 1, m = r >> 12;
        int ks = slot >> 3, ntl = slot & 7, g = lane >> 2, t = lane & 3;
        int n = half * 64 + ntl * 8 + g;     // n = kq*32 + j
        int kq = n >> 5, j = n & 31;
        const float* W = (m == 0) ? Wd1 : (m == 1) ? Wd2 : Wb;
        const float* src = W + (size_t)(j * KK + kq) * HH + ks * 16 + 2 * t;
        float f0 = src[0], f1 = src[1], f2 = src[8], f3 = src[9];
        g_Wg[m][half][slot][lane] = make_uint4(pack2(f0, f1), pack2(f2, f3),
                                               pack2(bres(f0), bres(f1)),
                                               pack2(bres(f2), bres(f3)));
    } else if (idx < 131072 + 12288 + 4096) {
        int r = idx - 131072 - 12288;
        int l = r & 63, hc = (r >> 6) & 15, k = r >> 10;
        int n = hc * 64 + l;
        int j = n >> 5, i = n & 31;
        g_bdre[k][hc][l] = bd[(i * ZZ + j) * KK + k];
    } else if (idx < 131072 + 12288 + 4096 + 384) {
        int r = idx - 147456;
        int n = r & 127, m = r >> 7;
        int kq = n >> 5, j = n & 31;
        const float* bv = (m == 0) ? bd1 : (m == 1) ? bd2 : bb;
        g_bdiag[m][n] = bv[j * KK + kq];
    }
}

__device__ __forceinline__ void mma_bf16(float c[4], const uint32_t a[4],
                                         uint32_t b0, uint32_t b1) {
    asm volatile(
        "mma.sync.aligned.m16n8k16.row.col.f32.bf16.bf16.f32 "
        "{%0,%1,%2,%3}, {%4,%5,%6,%7}, {%8,%9}, {%0,%1,%2,%3};"
        : "+f"(c[0]), "+f"(c[1]), "+f"(c[2]), "+f"(c[3])
        : "r"(a[0]), "r"(a[1]), "r"(a[2]), "r"(a[3]), "r"(b0), "r"(b1));
}
__device__ __forceinline__ void cp16(uint32_t dst, const void* src) {
    asm volatile("cp.async.cg.shared.global [%0], [%1], 16;" :: "r"(dst), "l"(src));
}
#define CP_COMMIT() asm volatile("cp.async.commit_group;" ::: "memory")
#define CP_WAIT0()  asm volatile("cp.async.wait_group 0;" ::: "memory")
#define CP_WAIT1()  asm volatile("cp.async.wait_group 1;" ::: "memory")

__device__ __forceinline__ uint32_t smem_u32(const void* p) {
    uint32_t a;
    asm("{ .reg .u64 t; cvta.to.shared.u64 t, %1; cvt.u32.u64 %0, t; }" : "=r"(a) : "l"(p));
    return a;
}

__device__ __forceinline__ void gemm_h(const uint4* __restrict__ Bq,
                                       int lane, int nq,
                                       const uint32_t aH[8][4],
                                       const uint32_t aL[8][4],
                                       float acc[4][4])
{
    #pragma unroll
    for (int q = 0; q < 4; q++)
        acc[q][0] = acc[q][1] = acc[q][2] = acc[q][3] = 0.f;
    #pragma unroll
    for (int ks = 0; ks < 8; ks++) {
        const int base = ks * 8 + nq * 4;
        uint4 b0 = Bq[(base + 0) * 32 + lane];
        uint4 b1 = Bq[(base + 1) * 32 + lane];
        uint4 b2 = Bq[(base + 2) * 32 + lane];
        uint4 b3 = Bq[(base + 3) * 32 + lane];
        mma_bf16(acc[0], aH[ks], b0.x, b0.y);
        mma_bf16(acc[1], aH[ks], b1.x, b1.y);
        mma_bf16(acc[2], aH[ks], b2.x, b2.y);
        mma_bf16(acc[3], aH[ks], b3.x, b3.y);
        mma_bf16(acc[0], aH[ks], b0.z, b0.w);
        mma_bf16(acc[1], aH[ks], b1.z, b1.w);
        mma_bf16(acc[2], aH[ks], b2.z, b2.w);
        mma_bf16(acc[3], aH[ks], b3.z, b3.w);
        mma_bf16(acc[0], aL[ks], b0.x, b0.y);
        mma_bf16(acc[1], aL[ks], b1.x, b1.y);
        mma_bf16(acc[2], aL[ks], b2.x, b2.y);
        mma_bf16(acc[3], aL[ks], b3.x, b3.y);
    }
}

__device__ __forceinline__ void stage32k(uint32_t dst, const void* srcv, int tid) {
    const char* s = (const char*)srcv;
    #pragma unroll
    for (int r = 0; r < 8; r++) {
        int i = r * NTH + tid;
        cp16(dst + i * 16, s + i * 16);
    }
}
__device__ __forceinline__ void stage_main(uint32_t sb, int buf, int hcg, int tid) {
    int k2 = hcg >> 4, hc = hcg & 15;
    stage32k(sb + (buf ? OFF_B1 : OFF_B0), &g_Wm[k2][hc][0][0], tid);
    if (tid < 16)
        cp16(sb + OFF_BB + buf * 256 + tid * 16,
             (const char*)&g_bdre[k2][hc][0] + tid * 16);
}

__global__ __launch_bounds__(NTH, 2)
void sylv_main(const float* __restrict__ z0, const float* __restrict__ h,
               float* __restrict__ out_z, float* __restrict__ out_ld)
{
    extern __shared__ char sm[];
    const uint32_t sb = smem_u32(sm);
    float* zsm = (float*)(sm + OFF_Z);

    const int tid = threadIdx.x, w = tid >> 5, lane = tid & 31;
    const int g = lane >> 2, t = lane & 3;
    const int r0 = (w & 3) * 16;
    const int nq = w >> 2;
    const int blk = blockIdx.x;
    const int m0 = blk * TM;
    const int msamp = tid >> 2, q = tid & 3;

    // ---- A fragments (persist): split bf16 hi/lo ----
    uint32_t aH[8][4], aL[8][4];
    {
        const float* hp = h + (size_t)m0 * HH;
        #pragma unroll
        for (int ks = 0; ks < 8; ks++) {
            int k0 = ks * 16 + 2 * t;
            const float* p0 = hp + (size_t)(r0 + g) * HH + k0;
            const float* p1 = hp + (size_t)(r0 + g + 8) * HH + k0;
            float2 x0 = *(const float2*)p0;
            float2 x1 = *(const float2*)p1;
            float2 x2 = *(const float2*)(p0 + 8);
            float2 x3 = *(const float2*)(p1 + 8);
            aH[ks][0] = pack2(x0.x, x0.y); aL[ks][0] = pack2(bres(x0.x), bres(x0.y));
            aH[ks][1] = pack2(x1.x, x1.y); aL[ks][1] = pack2(bres(x1.x), bres(x1.y));
            aH[ks][2] = pack2(x2.x, x2.y); aL[ks][2] = pack2(bres(x2.x), bres(x2.y));
            aH[ks][3] = pack2(x3.x, x3.y); aL[ks][3] = pack2(bres(x3.x), bres(x3.y));
        }
    }
    for (int idx = tid; idx < TM * ZZ; idx += NTH)
        zsm[(idx >> 5) * 33 + (idx & 31)] = z0[(size_t)(m0 + (idx >> 5)) * ZZ + (idx & 31)];

    const uint4* BqA = (const uint4*)(sm + OFF_B0);
    const uint4* BqB = (const uint4*)(sm + OFF_B1);

    // ---- diag GEMMs (6 half-chunks, double-buffered) -> global scratch ----
    stage32k(sb + OFF_B0, &g_Wg[0][0][0][0], tid);
    CP_COMMIT();
    for (int d = 0; d < 6; d++) {
        if (d < 5) {
            int dn = d + 1;
            stage32k(sb + ((dn & 1) ? OFF_B1 : OFF_B0), &g_Wg[dn >> 1][dn & 1][0][0], tid);
            CP_COMMIT(); CP_WAIT1();
        } else {
            CP_WAIT0();
        }
        __syncthreads();
        {
            int mm = d >> 1, half = d & 1;
            float acc[4][4];
            gemm_h((d & 1) ? BqB : BqA, lane, nq, aH, aL, acc);
            #pragma unroll
            for (int ntl = 0; ntl < 4; ntl++) {
                int lc = nq * 32 + ntl * 8 + 2 * t;
                int n = half * 64 + lc;
                float b0v = g_bdiag[mm][n], b1v = g_bdiag[mm][n + 1];
                float v0 = acc[ntl][0] + b0v, v1 = acc[ntl][1] + b1v;
                float v2 = acc[ntl][2] + b0v, v3 = acc[ntl][3] + b1v;
                if (mm < 2) { v0 = tanhf(v0); v1 = tanhf(v1); v2 = tanhf(v2); v3 = tanhf(v3); }
                g_dg[blk][mm][n][r0 + g]         = v0;
                g_dg[blk][mm][n + 1][r0 + g]     = v1;
                g_dg[blk][mm][n][r0 + g + 8]     = v2;
                g_dg[blk][mm][n + 1][r0 + g + 8] = v3;
            }
        }
        __syncthreads();
    }

    // ---- prologue: stage 0,1; gemm(0)->D0 ----
    stage_main(sb, 0, 0, tid); CP_COMMIT();
    stage_main(sb, 1, 1, tid); CP_COMMIT();
    CP_WAIT0();
    __syncthreads();
    {
        float acc[4][4];
        gemm_h(BqA, lane, nq, aH, aL, acc);
        float* Dd = (float*)(sm + OFF_D0);
        const float* bbp = (const float*)(sm + OFF_BB);
        #pragma unroll
        for (int ntl = 0; ntl < 4; ntl++) {
            int n0 = nq * 32 + ntl * 8 + 2 * t;
            float b0v = bbp[n0], b1v = bbp[n0 + 1];
            *(float2*)&Dd[(r0 + g) * DP + n0]     = make_float2(acc[ntl][0] + b0v, acc[ntl][1] + b1v);
            *(float2*)&Dd[(r0 + g + 8) * DP + n0] = make_float2(acc[ntl][2] + b0v, acc[ntl][3] + b1v);
        }
    }

    // hoisted pointers for the flow phase
    const float* dg1 = &g_dg[blk][0][0][0];
    const float* dg2 = &g_dg[blk][1][0][0];
    const float* dgb = &g_dg[blk][2][0][0];
    const float* zrow = zsm + msamp * 33;
    float* zroww = zsm + msamp * 33;

    // diag prefetch for cc=0
    float pf_d1[2], pf_d2[2], pf_b[2];
    pf_d1[0] = dg1[0 * 64 + msamp]; pf_d1[1] = dg1[1 * 64 + msamp];
    pf_d2[0] = dg2[0 * 64 + msamp]; pf_d2[1] = dg2[1 * 64 + msamp];
    pf_b[0]  = dgb[0 * 64 + msamp]; pf_b[1]  = dgb[1 * 64 + msamp];

    // ---- main loop: WAIT -> SYNC -> gemm -> stage -> storeD -> flow ----
    float zp[8], dz[8], ld_acc = 0.f;

    #pragma unroll 1
    for (int cc = 0; cc < 64; cc++) {
        const int k = cc >> 4, hc = cc & 15;
        const int fm = (k & 1) ? 31 : 0;       // XOR flip mask
        const int nx = cc + 1;
        const int j0 = hc * 2, j1 = j0 + 1;

        CP_WAIT0();
        __syncthreads();

        // consume prefetched diag; issue prefetch for cc+1 (overlaps MMAs)
        float d1v0 = pf_d1[0], d1v1 = pf_d1[1];
        float d2v0 = pf_d2[0], d2v1 = pf_d2[1];
        float bv0 = pf_b[0], bv1 = pf_b[1];
        if (nx < 64) {
            int kjn = ((nx >> 4) * 32 + (nx & 15) * 2) * 64 + msamp;
            pf_d1[0] = dg1[kjn]; pf_d1[1] = dg1[kjn + 64];
            pf_d2[0] = dg2[kjn]; pf_d2[1] = dg2[kjn + 64];
            pf_b[0]  = dgb[kjn]; pf_b[1]  = dgb[kjn + 64];
        }

        // GEMM chunk nx
        float acc[4][4];
        if (nx < 64)
            gemm_h((nx & 1) ? BqB : BqA, lane, nq, aH, aL, acc);

        // stage half-chunk cc+2 (safe: post-sync, last reader of buf[cc&1] was pre-sync)
        if (cc <= 61) { stage_main(sb, cc & 1, cc + 2, tid); CP_COMMIT(); }

        // store GEMM result for chunk nx
        if (nx < 64) {
            float* Dd = (float*)(sm + ((nx & 1) ? OFF_D1 : OFF_D0));
            const float* bbp = (const float*)(sm + OFF_BB + (nx & 1) * 256);
            #pragma unroll
            for (int ntl = 0; ntl < 4; ntl++) {
                int n0 = nq * 32 + ntl * 8 + 2 * t;
                float b0v = bbp[n0], b1v = bbp[n0 + 1];
                *(float2*)&Dd[(r0 + g) * DP + n0]     = make_float2(acc[ntl][0] + b0v, acc[ntl][1] + b1v);
                *(float2*)&Dd[(r0 + g + 8) * DP + n0] = make_float2(acc[ntl][2] + b0v, acc[ntl][3] + b1v);
            }
        }

        // ---- flow half-chunk cc (iteration end; desync absorbed by next gemm) ----
        {
            const float* Dc = (const float*)(sm + ((cc & 1) ? OFF_D1 : OFF_D0)) + msamp * DP;
            if (hc == 0) {
                #pragma unroll
                for (int il = 0; il < 8; il++) {
                    int gi = q * 8 + il;
                    zp[il] = zrow[gi ^ fm];
                    dz[il] = 0.f;
                }
            }
            float zpj0 = zrow[j0 ^ fm];
            float zpj1 = zrow[j1 ^ fm];

            float Dv[2][8];
            #pragma unroll
            for (int jj = 0; jj < 2; jj++) {
                const float4* p = (const float4*)&Dc[jj * 32 + q * 8];
                float4 x = p[0], y = p[1];
                Dv[jj][0] = x.x; Dv[jj][1] = x.y; Dv[jj][2] = x.z; Dv[jj][3] = x.w;
                Dv[jj][4] = y.x; Dv[jj][5] = y.y; Dv[jj][6] = y.z; Dv[jj][7] = y.w;
            }
            float p0 = 0.f, p1 = 0.f;
            #pragma unroll
            for (int il = 0; il < 8; il++) {
                int gi = q * 8 + il;
                p0 = fmaf(zp[il], (gi > j0) ? Dv[0][il] : 0.f, p0);
                p1 = fmaf(zp[il], (gi > j1) ? Dv[1][il] : 0.f, p1);
            }
            p0 += __shfl_xor_sync(0xffffffffu, p0, 1);
            p0 += __shfl_xor_sync(0xffffffffu, p0, 2);
            p1 += __shfl_xor_sync(0xffffffffu, p1, 1);
            p1 += __shfl_xor_sync(0xffffffffu, p1, 2);
            float t0 = tanhf(p0 + bv0 + zpj0 * d2v0);
            float t1 = tanhf(p1 + bv1 + zpj1 * d2v1);
            if (q == 0) {
                ld_acc += logf(fabsf(fmaf(1.f - t0 * t0, d1v0 * d2v0, 1.f)));
                ld_acc += logf(fabsf(fmaf(1.f - t1 * t1, d1v1 * d2v1, 1.f)));
            }
            #pragma unroll
            for (int il = 0; il < 8; il++) {
                int gi = q * 8 + il;
                float c0 = (gi < j0) ? Dv[0][il] : ((gi == j0) ? d1v0 : 0.f);
                float c1 = (gi < j1) ? Dv[1][il] : ((gi == j1) ? d1v1 : 0.f);
                dz[il] = fmaf(t0, c0, fmaf(t1, c1, dz[il]));
            }
            if (hc == 15) {
                #pragma unroll
                for (int il = 0; il < 8; il++) {
                    int gi = q * 8 + il;
                    zroww[gi ^ fm] += dz[il];
                }
            }
        }
    }
    __syncthreads();

    // ---- outputs ----
    if (q == 0) out_ld[m0 + msamp] = ld_acc;
    for (int idx = tid; idx < TM * ZZ; idx += NTH)
        out_z[(size_t)(m0 + (idx >> 5)) * ZZ + (idx & 31)] = zsm[(idx >> 5) * 33 + (idx & 31)];
}

extern "C" void kernel_launch(void* const* d_in, const int* in_sizes, int n_in,
                              void* d_out, int out_size)
{
    const float* z0  = (const float*)d_in[0];
    const float* h   = (const float*)d_in[1];
    const float* Wd  = (const float*)d_in[2];
    const float* bd  = (const float*)d_in[3];
    const float* Wd1 = (const float*)d_in[4];
    const float* bd1 = (const float*)d_in[5];
    const float* Wd2 = (const float*)d_in[6];
    const float* bd2 = (const float*)d_in[7];
    const float* Wb  = (const float*)d_in[8];
    const float* bb  = (const float*)d_in[9];

    const int B = in_sizes[0] / ZZ;          // 32768
    float* out_z  = (float*)d_out;
    float* out_ld = (float*)d_out + (size_t)B * ZZ;

    int prep_elems = 131072 + 12288 + 4096 + 384;
    prep_kernel<<<(prep_elems + 255) / 256, 256>>>(Wd, bd, Wd1, bd1, Wd2, bd2, Wb, bb);

    cudaFuncSetAttribute(sylv_main, cudaFuncAttributeMaxDynamicSharedMemorySize, SMEM_TOTAL);
    sylv_main<<<B / TM, NTH, SMEM_TOTAL>>>(z0, h, out_z, out_ld);
}